// round 10
// baseline (speedup 1.0000x reference)
#include <cuda_runtime.h>
#include <cuda_bf16.h>
#include <cstdint>

#define BATCH   32768
#define NSITES  64
#define NBULK   62
#define NHALF   31
#define TPB     128
#define SAMP_CTA 64                    // 2 L-warps x 32 samples (+ 2 R-warps, same samples)
#define NCTA    (BATCH / SAMP_CTA)     // 512

// Fragment-linear B operands, one array per chain direction:
// [slot][pass(4)][j(4)][lane(32)] x 16B;  pass: 0=M0h 1=M0l 2=Dh 3=Dl.
// L slot t = site t (B[n=e][k=d]); R slot t = site 61-t transposed (B[n=d][k=e]).
__device__ __align__(256) uint4 g_bfragsL[(NHALF + 1) * 4 * 4 * 32];
__device__ __align__(256) uint4 g_bfragsR[(NHALF + 1) * 4 * 4 * 32];

// ---------------- helpers ----------------
__device__ __forceinline__ void mma16816(float* d, const uint32_t* a, uint32_t b0, uint32_t b1) {
    asm volatile("mma.sync.aligned.m16n8k16.row.col.f32.bf16.bf16.f32 "
        "{%0,%1,%2,%3}, {%4,%5,%6,%7}, {%8,%9}, {%0,%1,%2,%3};"
        : "+f"(d[0]), "+f"(d[1]), "+f"(d[2]), "+f"(d[3])
        : "r"(a[0]), "r"(a[1]), "r"(a[2]), "r"(a[3]), "r"(b0), "r"(b1));
}
__device__ __forceinline__ void mma16816_z(float* d, const uint32_t* a, uint32_t b0, uint32_t b1,
                                           const float* z) {
    asm volatile("mma.sync.aligned.m16n8k16.row.col.f32.bf16.bf16.f32 "
        "{%0,%1,%2,%3}, {%4,%5,%6,%7}, {%8,%9}, {%10,%11,%12,%13};"
        : "=f"(d[0]), "=f"(d[1]), "=f"(d[2]), "=f"(d[3])
        : "r"(a[0]), "r"(a[1]), "r"(a[2]), "r"(a[3]), "r"(b0), "r"(b1),
          "f"(z[0]), "f"(z[1]), "f"(z[2]), "f"(z[3]));
}
__device__ __forceinline__ uint32_t packbf(float lo, float hi) {
    uint32_t r;
    asm("cvt.rn.bf16x2.f32 %0, %1, %2;" : "=r"(r) : "f"(hi), "f"(lo));
    return r;
}
__device__ __forceinline__ uint32_t packbf_trunc(uint32_t u0, uint32_t u1) {
    uint32_t r;
    asm("prmt.b32 %0, %1, %2, 0x7632;" : "=r"(r) : "r"(u0), "r"(u1));
    return r;
}
__device__ __forceinline__ void split2(float x0, float x1, uint32_t& hp, uint32_t& lp) {
    uint32_t u0 = __float_as_uint(x0), u1 = __float_as_uint(x1);
    hp = packbf_trunc(u0, u1);
    float l0 = x0 - __uint_as_float(u0 & 0xFFFF0000u);
    float l1 = x1 - __uint_as_float(u1 & 0xFFFF0000u);
    lp = packbf(l0, l1);
}

// ---------------- prep: fp32 bulk -> fragment-linear bf16 hi/lo B operands (L + R) ----------------
__global__ void prep_kernel(const float* __restrict__ bulk) {
    int s = blockIdx.x;                              // bulk site 0..61
    const float* base = bulk + s * 2048;             // [d][c][e]
    const int tr   = (s >= NHALF);                   // right-chain slot?
    const int slot = tr ? (NBULK - 1 - s) : s;
    uint32_t* dstw = tr ? (uint32_t*)g_bfragsR : (uint32_t*)g_bfragsL;

    for (int idx = threadIdx.x; idx < 2048; idx += blockDim.x) {
        int pass = idx >> 9;
        int j    = (idx >> 7) & 3;
        int lane = (idx >> 2) & 31;
        int m    = idx & 3;
        int n    = 8 * j + (lane >> 2);
        int k    = 8 * m + 2 * (lane & 3);
        float a0, b0, a1, b1;
        if (!tr) {   // B[n][k] = M[k][n]
            a0 = base[(k * 2 + 0) * 32 + n];       b0 = base[(k * 2 + 1) * 32 + n];
            a1 = base[((k + 1) * 2 + 0) * 32 + n]; b1 = base[((k + 1) * 2 + 1) * 32 + n];
        } else {     // B[n][k] = M[n][k]
            a0 = base[(n * 2 + 0) * 32 + k];       b0 = base[(n * 2 + 1) * 32 + k];
            a1 = base[(n * 2 + 0) * 32 + k + 1];   b1 = base[(n * 2 + 1) * 32 + k + 1];
        }
        float x0 = (pass >= 2) ? (b0 - a0) : a0;
        float x1 = (pass >= 2) ? (b1 - a1) : a1;
        float v0, v1;
        if (pass & 1) {
            __nv_bfloat16 h0 = __float2bfloat16(x0);
            __nv_bfloat16 h1 = __float2bfloat16(x1);
            v0 = x0 - __bfloat162float(h0);
            v1 = x1 - __bfloat162float(h1);
        } else { v0 = x0; v1 = x1; }
        dstw[((((slot * 4 + pass) * 4 + j) * 32 + lane) * 4) + m] = packbf(v0, v1);
    }
}

// ---------------- main kernel ----------------
// Warps 0,1 = LEFT chain (sites 1..31); warps 2,3 = RIGHT chain (sites 62..32, transposed).
// Barrier-free mainloop; join psi = u . v through SMEM at the end.
__global__ void __launch_bounds__(TPB, 4)
mps_mma_kernel(const int*   __restrict__ conf,
               const float* __restrict__ left,
               const float* __restrict__ right,
               float*       __restrict__ out)
{
    __shared__ unsigned long long masks_s[SAMP_CTA];
    __shared__ float lt_s[64];
    __shared__ float rt_s[64];
    __shared__ float vbuf[SAMP_CTA * 32];

    const int tid  = threadIdx.x;
    const int wid  = tid >> 5;
    const int lane = tid & 31;
    const int rowq = lane >> 2;
    const int q    = lane & 3;
    const int isR  = wid >> 1;         // 0 = left pair, 1 = right pair
    const int sgrp = wid & 1;          // sample group (32 samples) within CTA

    if (tid < 64) { lt_s[tid] = left[tid]; rt_s[tid] = right[tid]; }

    if (tid < SAMP_CTA) {
        unsigned long long mask = 0;
        const int4* cp4 = (const int4*)(conf + (size_t)(blockIdx.x * SAMP_CTA + tid) * NSITES);
        #pragma unroll
        for (int i = 0; i < NSITES / 4; i++) {
            int4 v = cp4[i];
            mask |= ((unsigned long long)(v.x & 1) << (4 * i))
                  | ((unsigned long long)(v.y & 1) << (4 * i + 1))
                  | ((unsigned long long)(v.z & 1) << (4 * i + 2))
                  | ((unsigned long long)(v.w & 1) << (4 * i + 3));
        }
        masks_s[tid] = mask;
    }
    __syncthreads();

    unsigned long long mr[4];
    #pragma unroll
    for (int k = 0; k < 4; k++) mr[k] = masks_s[sgrp * 32 + rowq + 8 * k];

    // ---- initial env as bf16 hi/lo A fragments ----
    uint32_t ah[2][2][4], al[2][2][4];   // [mtile][kt][reg]
    #pragma unroll
    for (int i = 0; i < 2; i++) {
        const int cA = isR ? (int)(mr[2 * i] >> 63)     : (int)(mr[2 * i] & 1ull);
        const int cB = isR ? (int)(mr[2 * i + 1] >> 63) : (int)(mr[2 * i + 1] & 1ull);
        #pragma unroll
        for (int kt = 0; kt < 2; kt++)
            #pragma unroll
            for (int h = 0; h < 2; h++) {
                int k0 = 16 * kt + 8 * h + 2 * q;
                float xA0, xA1, xB0, xB1;
                if (isR) {
                    xA0 = rt_s[k0 * 2 + cA];  xA1 = rt_s[(k0 + 1) * 2 + cA];
                    xB0 = rt_s[k0 * 2 + cB];  xB1 = rt_s[(k0 + 1) * 2 + cB];
                } else {
                    xA0 = lt_s[cA * 32 + k0]; xA1 = lt_s[cA * 32 + k0 + 1];
                    xB0 = lt_s[cB * 32 + k0]; xB1 = lt_s[cB * 32 + k0 + 1];
                }
                uint32_t hA, lA, hB, lB;
                split2(xA0, xA1, hA, lA);
                split2(xB0, xB1, hB, lB);
                ah[i][kt][2 * h]     = hA;  ah[i][kt][2 * h + 1] = hB;
                al[i][kt][2 * h]     = lA;  al[i][kt][2 * h + 1] = lB;
            }
    }

    const uint4* fb = (isR ? g_bfragsR : g_bfragsL) + lane;

    // prologue: slot 0, passes 0-1 (M0 hi+lo)
    uint4 bA[8], bB[8];
    #pragma unroll
    for (int j = 0; j < 4; j++) {
        bA[j]     = __ldg(fb + (0 * 4 + j) * 32);
        bA[4 + j] = __ldg(fb + (1 * 4 + j) * 32);
    }

    const float z4[4] = {0.0f, 0.0f, 0.0f, 0.0f};
    float acc[2][4][4];

    for (int t = 0; t < NHALF; t++) {
        // Δ-pass loads for slot t
        #pragma unroll
        for (int j = 0; j < 4; j++) {
            bB[j]     = __ldg(fb + (((t * 4 + 2) * 4) + j) * 32);
            bB[4 + j] = __ldg(fb + (((t * 4 + 3) * 4) + j) * 32);
        }

        // pass 1: acc = E * M0 (3 precision terms)
        #pragma unroll
        for (int j = 0; j < 4; j++) {
            #pragma unroll
            for (int i = 0; i < 2; i++) {
                float* a = acc[i][j];
                mma16816_z(a, ah[i][0], bA[j].x, bA[j].y, z4);
                mma16816(a, ah[i][1], bA[j].z, bA[j].w);
                mma16816(a, al[i][0], bA[j].x, bA[j].y);
                mma16816(a, al[i][1], bA[j].z, bA[j].w);
                mma16816(a, ah[i][0], bA[4 + j].x, bA[4 + j].y);
                mma16816(a, ah[i][1], bA[4 + j].z, bA[4 + j].w);
            }
        }

        // mask A fragments with this step's config bit
        {
            const int bitpos = isR ? (62 - t) : (t + 1);
            const uint32_t c0 = (uint32_t)((mr[0] >> bitpos) & 1ull);
            const uint32_t c1 = (uint32_t)((mr[1] >> bitpos) & 1ull);
            const uint32_t c2 = (uint32_t)((mr[2] >> bitpos) & 1ull);
            const uint32_t c3 = (uint32_t)((mr[3] >> bitpos) & 1ull);
            #pragma unroll
            for (int kt = 0; kt < 2; kt++)
                #pragma unroll
                for (int h = 0; h < 2; h++) {
                    ah[0][kt][2*h]   = c0 ? ah[0][kt][2*h]   : 0u;
                    al[0][kt][2*h]   = c0 ? al[0][kt][2*h]   : 0u;
                    ah[0][kt][2*h+1] = c1 ? ah[0][kt][2*h+1] : 0u;
                    al[0][kt][2*h+1] = c1 ? al[0][kt][2*h+1] : 0u;
                    ah[1][kt][2*h]   = c2 ? ah[1][kt][2*h]   : 0u;
                    al[1][kt][2*h]   = c2 ? al[1][kt][2*h]   : 0u;
                    ah[1][kt][2*h+1] = c3 ? ah[1][kt][2*h+1] : 0u;
                    al[1][kt][2*h+1] = c3 ? al[1][kt][2*h+1] : 0u;
                }
        }

        // next slot's M0-pass loads
        if (t + 1 < NHALF) {
            #pragma unroll
            for (int j = 0; j < 4; j++) {
                bA[j]     = __ldg(fb + ((((t + 1) * 4 + 0) * 4) + j) * 32);
                bA[4 + j] = __ldg(fb + ((((t + 1) * 4 + 1) * 4) + j) * 32);
            }
        }

        // pass 2: acc += E_masked * Delta (3 precision terms)
        #pragma unroll
        for (int j = 0; j < 4; j++) {
            #pragma unroll
            for (int i = 0; i < 2; i++) {
                float* a = acc[i][j];
                mma16816(a, ah[i][0], bB[j].x, bB[j].y);
                mma16816(a, ah[i][1], bB[j].z, bB[j].w);
                mma16816(a, al[i][0], bB[j].x, bB[j].y);
                mma16816(a, al[i][1], bB[j].z, bB[j].w);
                mma16816(a, ah[i][0], bB[4 + j].x, bB[4 + j].y);
                mma16816(a, ah[i][1], bB[4 + j].z, bB[4 + j].w);
            }
        }

        // split env (acc) -> next A fragments
        if (t + 1 < NHALF) {
            #pragma unroll
            for (int i = 0; i < 2; i++)
                #pragma unroll
                for (int kt = 0; kt < 2; kt++)
                    #pragma unroll
                    for (int h = 0; h < 2; h++) {
                        uint32_t hA, lA, hB, lB;
                        split2(acc[i][2 * kt + h][0], acc[i][2 * kt + h][1], hA, lA);
                        split2(acc[i][2 * kt + h][2], acc[i][2 * kt + h][3], hB, lB);
                        ah[i][kt][2 * h]     = hA;  ah[i][kt][2 * h + 1] = hB;
                        al[i][kt][2 * h]     = lA;  al[i][kt][2 * h + 1] = lB;
                    }
        }
    }

    // ---- join: psi = u . v ----
    if (isR) {
        #pragma unroll
        for (int i = 0; i < 2; i++)
            #pragma unroll
            for (int j = 0; j < 4; j++)
                #pragma unroll
                for (int r = 0; r < 4; r++) {
                    int row = sgrp * 32 + rowq + 16 * i + 8 * (r >> 1);
                    int col = 8 * j + 2 * q + (r & 1);
                    vbuf[row * 32 + col] = acc[i][j][r];
                }
    }
    __syncthreads();
    if (!isR) {
        float p[4];
        #pragma unroll
        for (int i = 0; i < 2; i++) {
            #pragma unroll
            for (int b = 0; b < 2; b++) {
                int row = sgrp * 32 + rowq + 16 * i + 8 * b;
                float s = 0.0f;
                #pragma unroll
                for (int j = 0; j < 4; j++) {
                    int col = 8 * j + 2 * q;
                    s += acc[i][j][2 * b]     * vbuf[row * 32 + col]
                       + acc[i][j][2 * b + 1] * vbuf[row * 32 + col + 1];
                }
                p[2 * i + b] = s;
            }
        }
        #pragma unroll
        for (int k = 0; k < 4; k++) {
            p[k] += __shfl_xor_sync(0xFFFFFFFF, p[k], 1);
            p[k] += __shfl_xor_sync(0xFFFFFFFF, p[k], 2);
        }
        if (q == 0) {
            int base = blockIdx.x * SAMP_CTA + sgrp * 32 + rowq;
            #pragma unroll
            for (int k = 0; k < 4; k++) out[base + 8 * k] = p[k];
        }
    }
}

extern "C" void kernel_launch(void* const* d_in, const int* in_sizes, int n_in,
                              void* d_out, int out_size) {
    const int*   conf  = (const int*)d_in[0];
    const float* left  = (const float*)d_in[1];
    const float* bulk  = (const float*)d_in[2];
    const float* right = (const float*)d_in[3];
    float*       out   = (float*)d_out;

    prep_kernel<<<NBULK, 256>>>(bulk);
    mps_mma_kernel<<<NCTA, TPB>>>(conf, left, right, out);
}

// round 11
// speedup vs baseline: 1.0547x; 1.0547x over previous
#include <cuda_runtime.h>
#include <cuda_bf16.h>
#include <cstdint>

#define BATCH   32768
#define NSITES  64
#define NBULK   62
#define TPB     128
#define SAMP_CTA 128                   // 4 warps x 32 samples
#define NCTA    (BATCH / SAMP_CTA)     // 256

// Fragment-linear B operands: [site][pass(4)][j(4)][lane(32)] x 16B.
// pass: 0=M0h, 1=M0l, 2=Dh, 3=Dl. One extra site of slop for the s+1 prefetch.
__device__ __align__(256) uint4 g_bfrags[(NBULK + 1) * 4 * 4 * 32];

// ---------------- helpers ----------------
// NOTE: not volatile — dataflow is fully captured by constraints, letting ptxas schedule.
__device__ __forceinline__ void mma16816(float* d, const uint32_t* a, uint32_t b0, uint32_t b1) {
    asm("mma.sync.aligned.m16n8k16.row.col.f32.bf16.bf16.f32 "
        "{%0,%1,%2,%3}, {%4,%5,%6,%7}, {%8,%9}, {%0,%1,%2,%3};"
        : "+f"(d[0]), "+f"(d[1]), "+f"(d[2]), "+f"(d[3])
        : "r"(a[0]), "r"(a[1]), "r"(a[2]), "r"(a[3]), "r"(b0), "r"(b1));
}
__device__ __forceinline__ void mma16816_z(float* d, const uint32_t* a, uint32_t b0, uint32_t b1,
                                           const float* z) {
    asm("mma.sync.aligned.m16n8k16.row.col.f32.bf16.bf16.f32 "
        "{%0,%1,%2,%3}, {%4,%5,%6,%7}, {%8,%9}, {%10,%11,%12,%13};"
        : "=f"(d[0]), "=f"(d[1]), "=f"(d[2]), "=f"(d[3])
        : "r"(a[0]), "r"(a[1]), "r"(a[2]), "r"(a[3]), "r"(b0), "r"(b1),
          "f"(z[0]), "f"(z[1]), "f"(z[2]), "f"(z[3]));
}
__device__ __forceinline__ uint32_t packbf(float lo, float hi) {
    uint32_t r;
    asm("cvt.rn.bf16x2.f32 %0, %1, %2;" : "=r"(r) : "f"(hi), "f"(lo));
    return r;
}
__device__ __forceinline__ uint32_t packbf_trunc(uint32_t u0, uint32_t u1) {
    uint32_t r;
    asm("prmt.b32 %0, %1, %2, 0x7632;" : "=r"(r) : "r"(u0), "r"(u1));
    return r;
}
__device__ __forceinline__ void split2(float x0, float x1, uint32_t& hp, uint32_t& lp) {
    uint32_t u0 = __float_as_uint(x0), u1 = __float_as_uint(x1);
    hp = packbf_trunc(u0, u1);
    float l0 = x0 - __uint_as_float(u0 & 0xFFFF0000u);
    float l1 = x1 - __uint_as_float(u1 & 0xFFFF0000u);
    lp = packbf(l0, l1);
}

// ---------------- prep: fp32 bulk -> fragment-linear bf16 hi/lo B operands ----------------
// reg m of lane l for block j = bf16 pair ( M[k][n], M[k+1][n] ), n = 8*j + (l>>2), k = 8*m + 2*(l&3)
__global__ void prep_kernel(const float* __restrict__ bulk) {
    int s = blockIdx.x;
    const float* base = bulk + s * 2048;            // [d][c][e]
    for (int idx = threadIdx.x; idx < 2048; idx += blockDim.x) {
        int pass = idx >> 9;                         // 0..3
        int j    = (idx >> 7) & 3;
        int lane = (idx >> 2) & 31;
        int m    = idx & 3;
        int n    = 8 * j + (lane >> 2);
        int k    = 8 * m + 2 * (lane & 3);
        float a0 = base[(k * 2 + 0) * 32 + n];
        float b0 = base[(k * 2 + 1) * 32 + n];
        float a1 = base[((k + 1) * 2 + 0) * 32 + n];
        float b1 = base[((k + 1) * 2 + 1) * 32 + n];
        float x0 = (pass >= 2) ? (b0 - a0) : a0;
        float x1 = (pass >= 2) ? (b1 - a1) : a1;
        float v0, v1;
        if (pass & 1) {
            __nv_bfloat16 h0 = __float2bfloat16(x0);
            __nv_bfloat16 h1 = __float2bfloat16(x1);
            v0 = x0 - __bfloat162float(h0);
            v1 = x1 - __bfloat162float(h1);
        } else { v0 = x0; v1 = x1; }
        ((uint32_t*)g_bfrags)[(((s * 4 + pass) * 4 + j) * 32 + lane) * 4 + m] = packbf(v0, v1);
    }
}

// ---------------- main kernel ----------------
// M=32 per warp, barrier-free mainloop, B via LDG.128 fragment loads.
// MMA issue is TERM-MAJOR: every consecutive group of 8 MMAs hits the 8 distinct
// accumulators before any repeats -> no intra-warp RAW chains.
__global__ void __launch_bounds__(TPB)
mps_mma_kernel(const int*   __restrict__ conf,
               const float* __restrict__ left,
               const float* __restrict__ right,
               float*       __restrict__ out)
{
    __shared__ unsigned long long masks_s[SAMP_CTA];
    __shared__ float lt_s[64];
    __shared__ float rt_s[64];

    const int tid  = threadIdx.x;
    const int wid  = tid >> 5;
    const int lane = tid & 31;
    const int rowq = lane >> 2;
    const int q    = lane & 3;

    if (tid < 64) { lt_s[tid] = left[tid]; rt_s[tid] = right[tid]; }

    {
        unsigned long long mask = 0;
        const int4* cp4 = (const int4*)(conf + (size_t)(blockIdx.x * SAMP_CTA + tid) * NSITES);
        #pragma unroll
        for (int i = 0; i < NSITES / 4; i++) {
            int4 v = cp4[i];
            mask |= ((unsigned long long)(v.x & 1) << (4 * i))
                  | ((unsigned long long)(v.y & 1) << (4 * i + 1))
                  | ((unsigned long long)(v.z & 1) << (4 * i + 2))
                  | ((unsigned long long)(v.w & 1) << (4 * i + 3));
        }
        masks_s[tid] = mask;
    }
    __syncthreads();

    unsigned long long mr[4];
    #pragma unroll
    for (int k = 0; k < 4; k++) mr[k] = masks_s[wid * 32 + rowq + 8 * k];

    // ---- initial env = left[c0] as bf16 hi/lo A fragments ----
    uint32_t ah[2][2][4], al[2][2][4];   // [mtile][kt][reg]
    #pragma unroll
    for (int i = 0; i < 2; i++) {
        const int cA = (int)(mr[2 * i] & 1ull);
        const int cB = (int)(mr[2 * i + 1] & 1ull);
        #pragma unroll
        for (int kt = 0; kt < 2; kt++)
            #pragma unroll
            for (int h = 0; h < 2; h++) {
                int k0 = 16 * kt + 8 * h + 2 * q;
                uint32_t hA, lA, hB, lB;
                split2(lt_s[cA * 32 + k0], lt_s[cA * 32 + k0 + 1], hA, lA);
                split2(lt_s[cB * 32 + k0], lt_s[cB * 32 + k0 + 1], hB, lB);
                ah[i][kt][2 * h]     = hA;  ah[i][kt][2 * h + 1] = hB;
                al[i][kt][2 * h]     = lA;  al[i][kt][2 * h + 1] = lB;
            }
    }

    const uint4* fb = g_bfrags + lane;

    // prologue: site 0, passes 0-1 (M0 hi+lo)
    uint4 bA[8], bB[8];
    #pragma unroll
    for (int j = 0; j < 4; j++) {
        bA[j]     = __ldg(fb + ((0 * 4 + 0) * 4 + j) * 32);
        bA[4 + j] = __ldg(fb + ((0 * 4 + 1) * 4 + j) * 32);
    }

    const float z4[4] = {0.0f, 0.0f, 0.0f, 0.0f};
    float acc[2][4][4];

    for (int s = 0; s < NBULK; s++) {
        // issue Δ-pass loads for site s
        #pragma unroll
        for (int j = 0; j < 4; j++) {
            bB[j]     = __ldg(fb + (((s * 4 + 2) * 4) + j) * 32);
            bB[4 + j] = __ldg(fb + (((s * 4 + 3) * 4) + j) * 32);
        }

        // ---- pass 1: acc = E * M0, term-major (8 independent MMAs per group) ----
        #pragma unroll
        for (int j = 0; j < 4; j++)
            #pragma unroll
            for (int i = 0; i < 2; i++)
                mma16816_z(acc[i][j], ah[i][0], bA[j].x, bA[j].y, z4);
        #pragma unroll
        for (int j = 0; j < 4; j++)
            #pragma unroll
            for (int i = 0; i < 2; i++)
                mma16816(acc[i][j], ah[i][1], bA[j].z, bA[j].w);
        #pragma unroll
        for (int j = 0; j < 4; j++)
            #pragma unroll
            for (int i = 0; i < 2; i++)
                mma16816(acc[i][j], al[i][0], bA[j].x, bA[j].y);
        #pragma unroll
        for (int j = 0; j < 4; j++)
            #pragma unroll
            for (int i = 0; i < 2; i++)
                mma16816(acc[i][j], al[i][1], bA[j].z, bA[j].w);
        #pragma unroll
        for (int j = 0; j < 4; j++)
            #pragma unroll
            for (int i = 0; i < 2; i++)
                mma16816(acc[i][j], ah[i][0], bA[4 + j].x, bA[4 + j].y);
        #pragma unroll
        for (int j = 0; j < 4; j++)
            #pragma unroll
            for (int i = 0; i < 2; i++)
                mma16816(acc[i][j], ah[i][1], bA[4 + j].z, bA[4 + j].w);

        // ---- mask A fragments in place with site-(s+1) bits ----
        {
            const uint32_t c0 = (uint32_t)((mr[0] >> (s + 1)) & 1ull);
            const uint32_t c1 = (uint32_t)((mr[1] >> (s + 1)) & 1ull);
            const uint32_t c2 = (uint32_t)((mr[2] >> (s + 1)) & 1ull);
            const uint32_t c3 = (uint32_t)((mr[3] >> (s + 1)) & 1ull);
            #pragma unroll
            for (int kt = 0; kt < 2; kt++)
                #pragma unroll
                for (int h = 0; h < 2; h++) {
                    ah[0][kt][2*h]   = c0 ? ah[0][kt][2*h]   : 0u;
                    al[0][kt][2*h]   = c0 ? al[0][kt][2*h]   : 0u;
                    ah[0][kt][2*h+1] = c1 ? ah[0][kt][2*h+1] : 0u;
                    al[0][kt][2*h+1] = c1 ? al[0][kt][2*h+1] : 0u;
                    ah[1][kt][2*h]   = c2 ? ah[1][kt][2*h]   : 0u;
                    al[1][kt][2*h]   = c2 ? al[1][kt][2*h]   : 0u;
                    ah[1][kt][2*h+1] = c3 ? ah[1][kt][2*h+1] : 0u;
                    al[1][kt][2*h+1] = c3 ? al[1][kt][2*h+1] : 0u;
                }
        }

        // issue next site's M0-pass loads
        if (s + 1 < NBULK) {
            #pragma unroll
            for (int j = 0; j < 4; j++) {
                bA[j]     = __ldg(fb + ((((s + 1) * 4 + 0) * 4) + j) * 32);
                bA[4 + j] = __ldg(fb + ((((s + 1) * 4 + 1) * 4) + j) * 32);
            }
        }

        // ---- pass 2: acc += E_masked * Delta, term-major ----
        #pragma unroll
        for (int j = 0; j < 4; j++)
            #pragma unroll
            for (int i = 0; i < 2; i++)
                mma16816(acc[i][j], ah[i][0], bB[j].x, bB[j].y);
        #pragma unroll
        for (int j = 0; j < 4; j++)
            #pragma unroll
            for (int i = 0; i < 2; i++)
                mma16816(acc[i][j], ah[i][1], bB[j].z, bB[j].w);
        #pragma unroll
        for (int j = 0; j < 4; j++)
            #pragma unroll
            for (int i = 0; i < 2; i++)
                mma16816(acc[i][j], al[i][0], bB[j].x, bB[j].y);
        #pragma unroll
        for (int j = 0; j < 4; j++)
            #pragma unroll
            for (int i = 0; i < 2; i++)
                mma16816(acc[i][j], al[i][1], bB[j].z, bB[j].w);
        #pragma unroll
        for (int j = 0; j < 4; j++)
            #pragma unroll
            for (int i = 0; i < 2; i++)
                mma16816(acc[i][j], ah[i][0], bB[4 + j].x, bB[4 + j].y);
        #pragma unroll
        for (int j = 0; j < 4; j++)
            #pragma unroll
            for (int i = 0; i < 2; i++)
                mma16816(acc[i][j], ah[i][1], bB[4 + j].z, bB[4 + j].w);

        // ---- split selected env (acc) -> next A fragments ----
        if (s + 1 < NBULK) {
            #pragma unroll
            for (int i = 0; i < 2; i++)
                #pragma unroll
                for (int kt = 0; kt < 2; kt++)
                    #pragma unroll
                    for (int h = 0; h < 2; h++) {
                        uint32_t hA, lA, hB, lB;
                        split2(acc[i][2 * kt + h][0], acc[i][2 * kt + h][1], hA, lA);
                        split2(acc[i][2 * kt + h][2], acc[i][2 * kt + h][3], hB, lB);
                        ah[i][kt][2 * h]     = hA;  ah[i][kt][2 * h + 1] = hB;
                        al[i][kt][2 * h]     = lA;  al[i][kt][2 * h + 1] = lB;
                    }
        }
    }

    // ---- final dot with right[:, c63]; reduce across the 4 lanes of each row group ----
    float p[4];
    #pragma unroll
    for (int i = 0; i < 2; i++) {
        const int cA = (int)(mr[2 * i]     >> 63);
        const int cB = (int)(mr[2 * i + 1] >> 63);
        float pa = 0.0f, pb = 0.0f;
        #pragma unroll
        for (int j = 0; j < 4; j++) {
            int n0 = 8 * j + 2 * q;
            pa += acc[i][j][0] * rt_s[n0 * 2 + cA] + acc[i][j][1] * rt_s[(n0 + 1) * 2 + cA];
            pb += acc[i][j][2] * rt_s[n0 * 2 + cB] + acc[i][j][3] * rt_s[(n0 + 1) * 2 + cB];
        }
        p[2 * i]     = pa;
        p[2 * i + 1] = pb;
    }
    #pragma unroll
    for (int k = 0; k < 4; k++) {
        p[k] += __shfl_xor_sync(0xFFFFFFFF, p[k], 1);
        p[k] += __shfl_xor_sync(0xFFFFFFFF, p[k], 2);
    }
    if (q == 0) {
        int base = blockIdx.x * SAMP_CTA + wid * 32 + rowq;
        #pragma unroll
        for (int k = 0; k < 4; k++) out[base + 8 * k] = p[k];
    }
}

extern "C" void kernel_launch(void* const* d_in, const int* in_sizes, int n_in,
                              void* d_out, int out_size) {
    const int*   conf  = (const int*)d_in[0];
    const float* left  = (const float*)d_in[1];
    const float* bulk  = (const float*)d_in[2];
    const float* right = (const float*)d_in[3];
    float*       out   = (float*)d_out;

    prep_kernel<<<NBULK, 256>>>(bulk);
    mps_mma_kernel<<<NCTA, TPB>>>(conf, left, right, out);
}